// round 15
// baseline (speedup 1.0000x reference)
#include <cuda_runtime.h>
#include <cuda_fp16.h>
#include <cstdint>

#define BB  8
#define SQL 512
#define SKL 512
#define HH  768
#define NHD 12
#define DHD 64
#define MROWS (BB * SQL)   // 4096

#define C2 0.1803368801111244f   // 0.125 * log2(e)

// ---------------- scratch ----------------
__device__ float g_P2[SQL * SKL];
__device__ __half g_qh[MROWS * HH];
__device__ __half g_kh[MROWS * HH];
__device__ __half g_vh[MROWS * HH];
__device__ __half g_hid[MROWS * HH];
__device__ __half g_ctx[MROWS * HH];
__device__ __half g_w[3 * HH * HH];

// ---------------- helpers ----------------
__device__ __forceinline__ float ex2f(float x) {
    float y;
    asm("ex2.approx.ftz.f32 %0, %1;" : "=f"(y) : "f"(x));
    return y;
}
__device__ __forceinline__ uint32_t smem_u32(const void* p) {
    uint32_t a;
    asm("{ .reg .u64 t; cvta.to.shared.u64 t, %1; cvt.u32.u64 %0, t; }" : "=r"(a) : "l"(p));
    return a;
}
__device__ __forceinline__ void cpa16(uint32_t dst, const void* src) {
    asm volatile("cp.async.cg.shared.global [%0], [%1], 16;" :: "r"(dst), "l"(src));
}
#define CPA_COMMIT() asm volatile("cp.async.commit_group;" ::: "memory")
#define CPA_WAIT(n)  asm volatile("cp.async.wait_group %0;" :: "n"(n) : "memory")

__device__ __forceinline__ void mma16816(float* d, const uint32_t* a, const uint32_t* b)
{
    asm volatile(
        "mma.sync.aligned.m16n8k16.row.col.f32.f16.f16.f32 "
        "{%0,%1,%2,%3}, {%4,%5,%6,%7}, {%8,%9}, {%0,%1,%2,%3};"
        : "+f"(d[0]), "+f"(d[1]), "+f"(d[2]), "+f"(d[3])
        : "r"(a[0]), "r"(a[1]), "r"(a[2]), "r"(a[3]), "r"(b[0]), "r"(b[1]));
}
__device__ __forceinline__ void ldmx4(uint32_t* r, uint32_t addr)
{
    asm volatile("ldmatrix.sync.aligned.m8n8.x4.shared.b16 {%0,%1,%2,%3}, [%4];"
                 : "=r"(r[0]), "=r"(r[1]), "=r"(r[2]), "=r"(r[3]) : "r"(addr));
}
__device__ __forceinline__ void ldmx4t(uint32_t* r, uint32_t addr)
{
    asm volatile("ldmatrix.sync.aligned.m8n8.x4.trans.shared.b16 {%0,%1,%2,%3}, [%4];"
                 : "=r"(r[0]), "=r"(r[1]), "=r"(r[2]), "=r"(r[3]) : "r"(addr));
}
__device__ __forceinline__ uint32_t pack_hf2(float a, float b) {
    __half2 h = __floats2half2_rn(a, b);
    return *(uint32_t*)&h;
}

// ---------------------------------------------------------------------------
// prep: y=0..4 -> fp32->fp16 conversion of 5 arrays; y=5 -> P2 = pos@pos^T*C2.
// ---------------------------------------------------------------------------
__global__ __launch_bounds__(256) void prep(
    const float* __restrict__ hidden, const float* __restrict__ context,
    const float* __restrict__ Wq, const float* __restrict__ Wk, const float* __restrict__ Wv,
    const float* __restrict__ pos,
    __half* __restrict__ hh, __half* __restrict__ ch, __half* __restrict__ w,
    float* __restrict__ P2)
{
    __shared__ float As[64][68];
    __shared__ float Bs[64][68];

    const int y = blockIdx.y;
    const int t = threadIdx.x;

    if (y == 5) {
        // ---- P2 tile: 64x64, 8x8 tile grid, only blocks x<64 active ----
        if (blockIdx.x >= 64) return;
        const int m0 = (blockIdx.x >> 3) << 6;
        const int n0 = (blockIdx.x & 7) << 6;

        // load 64x64 fp32 tiles of pos, stored transposed [k][row]
#pragma unroll
        for (int i = 0; i < 4; i++) {
            int idx = t + (i << 8);     // 0..1023
            int row = idx >> 4;
            int c4  = (idx & 15) << 2;
            float4 va = *(const float4*)(pos + (size_t)(m0 + row) * DHD + c4);
            As[c4 + 0][row] = va.x; As[c4 + 1][row] = va.y;
            As[c4 + 2][row] = va.z; As[c4 + 3][row] = va.w;
            float4 vb = *(const float4*)(pos + (size_t)(n0 + row) * DHD + c4);
            Bs[c4 + 0][row] = vb.x; Bs[c4 + 1][row] = vb.y;
            Bs[c4 + 2][row] = vb.z; Bs[c4 + 3][row] = vb.w;
        }
        __syncthreads();

        const int tm = (t >> 4) << 2;   // 16 groups x 4 rows
        const int tn = (t & 15) << 2;   // 16 groups x 4 cols
        float acc[4][4];
#pragma unroll
        for (int i = 0; i < 4; i++)
#pragma unroll
            for (int j = 0; j < 4; j++) acc[i][j] = 0.0f;

#pragma unroll 8
        for (int kk = 0; kk < 64; kk++) {
            float a[4], b[4];
            *(float4*)a = *(const float4*)&As[kk][tm];
            *(float4*)b = *(const float4*)&Bs[kk][tn];
#pragma unroll
            for (int i = 0; i < 4; i++)
#pragma unroll
                for (int j = 0; j < 4; j++)
                    acc[i][j] += a[i] * b[j];
        }

#pragma unroll
        for (int i = 0; i < 4; i++)
#pragma unroll
            for (int j = 0; j < 4; j++)
                P2[(size_t)(m0 + tm + i) * SKL + n0 + tn + j] = acc[i][j] * C2;
        return;
    }

    // ---- fp32 -> fp16 conversion ----
    const float* x;
    __half* hi;
    int n4;
    const int nA4 = MROWS * HH / 4, nW4 = HH * HH / 4;
    switch (y) {
        case 0: x = hidden;  hi = hh;              n4 = nA4; break;
        case 1: x = context; hi = ch;              n4 = nA4; break;
        case 2: x = Wq;      hi = w;               n4 = nW4; break;
        case 3: x = Wk;      hi = w + HH * HH;     n4 = nW4; break;
        default:x = Wv;      hi = w + 2 * HH * HH; n4 = nW4; break;
    }
    int i = blockIdx.x * blockDim.x + t;
    if (i >= n4) return;
    float4 v = ((const float4*)x)[i];
    __half2 a, b;
    a.x = __float2half_rn(v.x); a.y = __float2half_rn(v.y);
    b.x = __float2half_rn(v.z); b.y = __float2half_rn(v.w);
    ((__half2*)hi)[2 * i] = a; ((__half2*)hi)[2 * i + 1] = b;
}

// ---------------------------------------------------------------------------
// QKV projection: 1-term fp16 HMMA, BK=64, 2-stage, two-barrier (R10 form).
// ---------------------------------------------------------------------------
#define QPAD 72
#define QTIL 18432
#define QSTG 36864

__global__ __launch_bounds__(256, 2) void qkv_hmma(
    const __half* __restrict__ hid, const __half* __restrict__ ctx,
    const __half* __restrict__ w,
    const float* __restrict__ bq, const float* __restrict__ bk, const float* __restrict__ bv,
    const float* __restrict__ pos,
    __half* __restrict__ qh, __half* __restrict__ kh, __half* __restrict__ vh)
{
    extern __shared__ char smc[];
    const uint32_t sb = smem_u32(smc);

    const int z = blockIdx.z;
    const __half* A = (z == 0) ? hid : ctx;
    const __half* B = w + (size_t)z * HH * HH;
    const float* bias = (z == 0) ? bq : ((z == 1) ? bk : bv);
    __half* outp = (z == 0) ? qh : ((z == 1) ? kh : vh);

    const int t    = threadIdx.x;
    const int lane = t & 31;
    const int wid  = t >> 5;
    const int wm   = wid & 3;
    const int wn   = wid >> 2;
    const int g    = lane >> 2;
    const int tig  = lane & 3;
    const int m0   = blockIdx.y << 7;
    const int n0   = blockIdx.x << 7;

    const uint32_t a_off = ((wm * 32 + (lane & 15)) * QPAD + ((lane >> 4) << 3)) * 2;
    const uint32_t b_off = ((wn * 64 + (lane & 7) + ((lane & 16) ? 8 : 0)) * QPAD
                            + (((lane >> 3) & 1) << 3)) * 2;

    float acc[2][8][4];
#pragma unroll
    for (int i = 0; i < 2; i++)
#pragma unroll
        for (int j = 0; j < 8; j++)
#pragma unroll
            for (int c = 0; c < 4; c++) acc[i][j][c] = 0.0f;

    auto issue = [&](int kt, int stg) {
        const int k0 = kt << 6;
        const uint32_t base = sb + stg * QSTG;
#pragma unroll
        for (int i = 0; i < 4; i++) {
            int idx = t + (i << 8);
            int row = idx >> 3;
            int c   = (idx & 7) << 3;
            uint32_t so = row * 144 + c * 2;
            cpa16(base + so,        A + (size_t)(m0 + row) * HH + k0 + c);
            cpa16(base + QTIL + so, B + (size_t)(n0 + row) * HH + k0 + c);
        }
    };

    issue(0, 0);
    CPA_COMMIT();

    const int NT = HH / 64;   // 12
    for (int kt = 0; kt < NT; kt++) {
        if (kt + 1 < NT) {
            issue(kt + 1, (kt + 1) & 1);
            CPA_COMMIT();
            CPA_WAIT(1);
        } else {
            CPA_WAIT(0);
        }
        __syncthreads();

        const uint32_t stga = sb + (kt & 1) * QSTG;
        const uint32_t pA = stga + a_off;
        const uint32_t pB = stga + QTIL + b_off;

#pragma unroll
        for (int kk = 0; kk < 4; kk++) {
            const uint32_t kb = kk * 32;
            uint32_t bfr[8][2];
#pragma unroll
            for (int np = 0; np < 4; np++) {
                uint32_t r[4];
                ldmx4(r, pB + np * (16 * QPAD * 2) + kb);
                bfr[2 * np][0] = r[0];     bfr[2 * np][1] = r[1];
                bfr[2 * np + 1][0] = r[2]; bfr[2 * np + 1][1] = r[3];
            }
            uint32_t af[2][4];
            ldmx4(af[0], pA + kb);
            ldmx4(af[1], pA + 16 * QPAD * 2 + kb);
#pragma unroll
            for (int mt = 0; mt < 2; mt++)
#pragma unroll
                for (int nt = 0; nt < 8; nt++)
                    mma16816(acc[mt][nt], af[mt], bfr[nt]);
        }
        __syncthreads();
    }

#pragma unroll
    for (int mt = 0; mt < 2; mt++) {
#pragma unroll
        for (int nt = 0; nt < 8; nt++) {
            int m = m0 + wm * 32 + mt * 16 + g;
            int n = n0 + wn * 64 + nt * 8 + 2 * tig;
            float b0 = bias[n], b1 = bias[n + 1];
#pragma unroll
            for (int half = 0; half < 2; half++) {
                int mm = m + half * 8;
                float f0 = acc[mt][nt][2 * half]     + b0;
                float f1 = acc[mt][nt][2 * half + 1] + b1;
                if (z == 1) {
                    f0 += pos[(mm & (SKL - 1)) * DHD + (n & (DHD - 1))];
                    f1 += pos[(mm & (SKL - 1)) * DHD + ((n + 1) & (DHD - 1))];
                }
                *(uint32_t*)(outp + (size_t)mm * HH + n) = pack_hf2(f0, f1);
            }
        }
    }
}

// ---------------------------------------------------------------------------
// Flash attention: R14 form (64 q-rows/CTA, 128 threads, occ 4, hoisted Q,
// single barrier per k-tile, 2-stage KV).
// smem: Q 9216 | KV 2x18432 | mask 2048 = 48128
// ---------------------------------------------------------------------------
#define FP   72
#define OKV  9216
#define KSTG 18432
#define KTIL 9216
#define OMB  (OKV + 2 * KSTG)   // 46080
#define FSM  (OMB + 2048)       // 48128

__global__ __launch_bounds__(128, 4) void flash_hmma(
    const __half* __restrict__ qh,
    const __half* __restrict__ kh, const __half* __restrict__ vh,
    const float* __restrict__ P2, const int* __restrict__ mask,
    float* __restrict__ out)
{
    extern __shared__ char smc[];
    __half* sQh = (__half*)(smc);
    float*  smb = (float*)(smc + OMB);
    const uint32_t sb = smem_u32(smc);

    const int t    = threadIdx.x;
    const int lane = t & 31;
    const int w    = t >> 5;
    const int g    = lane >> 2;
    const int tig  = lane & 3;
    const int wr   = w << 4;
    const int b    = blockIdx.z;
    const int h    = blockIdx.y;
    const int q0   = blockIdx.x << 6;

    const uint32_t q_off = ((wr + (lane & 15)) * FP + ((lane >> 4) << 3)) * 2;
    const uint32_t k_off = (((lane & 7) + ((lane & 16) ? 8 : 0)) * FP
                            + (((lane >> 3) & 1) << 3)) * 2;
    const uint32_t v_off = ((lane & 15) * FP + ((lane >> 4) << 3)) * 2;

    auto issue_kv = [&](int kt, int stg) {
        const uint32_t base = sb + OKV + stg * KSTG;
#pragma unroll
        for (int i = 0; i < 4; i++) {
            int idx = t + (i << 7);
            int row = idx >> 3;
            int c   = (idx & 7) << 3;
            uint32_t so = row * 144 + c * 2;
            size_t gg = (size_t)(b * SKL + kt * 64 + row) * HH + h * DHD + c;
            cpa16(base + so,        kh + gg);
            cpa16(base + KTIL + so, vh + gg);
        }
    };

    issue_kv(0, 0);
    CPA_COMMIT();

#pragma unroll
    for (int i = 0; i < 4; i++) {
        int idx = t + (i << 7);
        int row = idx >> 3;
        int c   = (idx & 7) << 3;
        size_t gsrc = (size_t)(b * SQL + q0 + row) * HH + h * DHD + c;
        *(uint4*)(sQh + row * FP + c) = *(const uint4*)(qh + gsrc);
    }
#pragma unroll
    for (int i = 0; i < 4; i++) {
        int idx = t + (i << 7);
        smb[idx] = (mask[b * SKL + idx] == 0) ? -1e30f : 0.0f;
    }
    __syncthreads();

    uint32_t qfr[4][4];
#pragma unroll
    for (int kk = 0; kk < 4; kk++)
        ldmx4(qfr[kk], sb + q_off + kk * 32);

    float o[8][4];
#pragma unroll
    for (int i = 0; i < 8; i++)
#pragma unroll
        for (int c = 0; c < 4; c++) o[i][c] = 0.0f;
    float m0r = -1e30f, m1r = -1e30f, l0r = 0.0f, l1r = 0.0f;

    const int NT = SKL / 64;   // 8
    for (int kt = 0; kt < NT; kt++) {
        CPA_WAIT(0);
        __syncthreads();
        if (kt + 1 < NT) {
            issue_kv(kt + 1, (kt + 1) & 1);
            CPA_COMMIT();
        }

        const int stg = kt & 1;
        const uint32_t kvb = sb + OKV + stg * KSTG;
        const uint32_t pK = kvb + k_off;
        const uint32_t pV = kvb + KTIL + v_off;

        // ---- S = Q K'^T ----
        float s[8][4];
#pragma unroll
        for (int nt = 0; nt < 8; nt++)
#pragma unroll
            for (int c = 0; c < 4; c++) s[nt][c] = 0.0f;

#pragma unroll
        for (int kk = 0; kk < 4; kk++) {
            const uint32_t kb = kk * 32;
#pragma unroll
            for (int np = 0; np < 4; np++) {
                uint32_t bh4[4];
                ldmx4(bh4, pK + np * (16 * FP * 2) + kb);
                mma16816(s[2 * np],     qfr[kk], bh4 + 0);
                mma16816(s[2 * np + 1], qfr[kk], bh4 + 2);
            }
        }

        // ---- bias + mask + online softmax ----
        const float* pg0 = P2 + (size_t)(q0 + wr + g) * SKL + kt * 64;
        const float* pg1 = pg0 + 8 * SKL;
        const float* mrow = smb + kt * 64;
        float vm0 = -1e30f, vm1 = -1e30f;
#pragma unroll
        for (int nt = 0; nt < 8; nt++) {
            int cc = nt * 8 + 2 * tig;
            float2 p0 = *(const float2*)(pg0 + cc);
            float2 p1 = *(const float2*)(pg1 + cc);
            float mb0 = mrow[cc], mb1 = mrow[cc + 1];
            s[nt][0] = fmaf(s[nt][0], C2, p0.x) + mb0;
            s[nt][1] = fmaf(s[nt][1], C2, p0.y) + mb1;
            s[nt][2] = fmaf(s[nt][2], C2, p1.x) + mb0;
            s[nt][3] = fmaf(s[nt][3], C2, p1.y) + mb1;
            vm0 = fmaxf(vm0, fmaxf(s[nt][0], s[nt][1]));
            vm1 = fmaxf(vm1, fmaxf(s[nt][2], s[nt][3]));
        }
        vm0 = fmaxf(vm0, __shfl_xor_sync(0xffffffffu, vm0, 1));
        vm0 = fmaxf(vm0, __shfl_xor_sync(0xffffffffu, vm0, 2));
        vm1 = fmaxf(vm1, __shfl_xor_sync(0xffffffffu, vm1, 1));
        vm1 = fmaxf(vm1, __shfl_xor_sync(0xffffffffu, vm1, 2));
        float mn0 = fmaxf(m0r, vm0), mn1 = fmaxf(m1r, vm1);
        float cr0 = ex2f(m0r - mn0), cr1 = ex2f(m1r - mn1);
        m0r = mn0; m1r = mn1;

        float rs0 = 0.0f, rs1 = 0.0f;
#pragma unroll
        for (int nt = 0; nt < 8; nt++) {
            s[nt][0] = ex2f(s[nt][0] - mn0); rs0 += s[nt][0];
            s[nt][1] = ex2f(s[nt][1] - mn0); rs0 += s[nt][1];
            s[nt][2] = ex2f(s[nt][2] - mn1); rs1 += s[nt][2];
            s[nt][3] = ex2f(s[nt][3] - mn1); rs1 += s[nt][3];
        }
        rs0 += __shfl_xor_sync(0xffffffffu, rs0, 1);
        rs0 += __shfl_xor_sync(0xffffffffu, rs0, 2);
        rs1 += __shfl_xor_sync(0xffffffffu, rs1, 1);
        rs1 += __shfl_xor_sync(0xffffffffu, rs1, 2);
        l0r = l0r * cr0 + rs0;
        l1r = l1r * cr1 + rs1;
#pragma unroll
        for (int nt = 0; nt < 8; nt++) {
            o[nt][0] *= cr0; o[nt][1] *= cr0;
            o[nt][2] *= cr1; o[nt][3] *= cr1;
        }

        // ---- O += P @ V ----
#pragma unroll
        for (int j = 0; j < 4; j++) {
            const int na = 2 * j, nb = 2 * j + 1;
            uint32_t aph[4];
            aph[0] = pack_hf2(s[na][0], s[na][1]);
            aph[1] = pack_hf2(s[na][2], s[na][3]);
            aph[2] = pack_hf2(s[nb][0], s[nb][1]);
            aph[3] = pack_hf2(s[nb][2], s[nb][3]);
            const uint32_t jv = pV + j * (16 * FP * 2);
#pragma unroll
            for (int vp = 0; vp < 4; vp++) {
                uint32_t bv4[4];
                ldmx4t(bv4, jv + vp * 32);
                mma16816(o[2 * vp],     aph, bv4 + 0);
                mma16816(o[2 * vp + 1], aph, bv4 + 2);
            }
        }
    }

    float inv0 = 1.0f / l0r, inv1 = 1.0f / l1r;
    float* or0 = out + (size_t)(b * SQL + q0 + wr + g) * HH + h * DHD;
    float* or1 = or0 + 8 * HH;
#pragma unroll
    for (int ntv = 0; ntv < 8; ntv++) {
        int cc = ntv * 8 + 2 * tig;
        float2 w0 = make_float2(o[ntv][0] * inv0, o[ntv][1] * inv0);
        float2 w1 = make_float2(o[ntv][2] * inv1, o[ntv][3] * inv1);
        *(float2*)(or0 + cc) = w0;
        *(float2*)(or1 + cc) = w1;
    }
}

// ---------------------------------------------------------------------------
extern "C" void kernel_launch(void* const* d_in, const int* in_sizes, int n_in,
                              void* d_out, int out_size)
{
    const float* hidden  = (const float*)d_in[0];
    const float* context = (const float*)d_in[1];
    const int*   mask    = (const int*)d_in[2];
    const float* Wq      = (const float*)d_in[3];
    const float* bq      = (const float*)d_in[4];
    const float* Wk      = (const float*)d_in[5];
    const float* bk      = (const float*)d_in[6];
    const float* Wv      = (const float*)d_in[7];
    const float* bv      = (const float*)d_in[8];
    const float* pos     = (const float*)d_in[9];
    float* out = (float*)d_out;

    float* P2;
    cudaGetSymbolAddress((void**)&P2, g_P2);
    __half *qh, *kh, *vh, *hh, *ch, *w;
    cudaGetSymbolAddress((void**)&qh, g_qh);
    cudaGetSymbolAddress((void**)&kh, g_kh);
    cudaGetSymbolAddress((void**)&vh, g_vh);
    cudaGetSymbolAddress((void**)&hh, g_hid);
    cudaGetSymbolAddress((void**)&ch, g_ctx);
    cudaGetSymbolAddress((void**)&w,  g_w);

    // fused conversions + P2 in ONE launch
    const int nA4 = MROWS * HH / 4;
    dim3 gprep((nA4 + 255) / 256, 6);
    prep<<<gprep, 256>>>(hidden, context, Wq, Wk, Wv, pos, hh, ch, w, P2);

    cudaFuncSetAttribute(qkv_hmma, cudaFuncAttributeMaxDynamicSharedMemorySize, 2 * QSTG);
    dim3 gproj(HH / 128, MROWS / 128, 3);
    qkv_hmma<<<gproj, 256, 2 * QSTG>>>(hh, ch, w, bq, bk, bv, pos, qh, kh, vh);

    cudaFuncSetAttribute(flash_hmma, cudaFuncAttributeMaxDynamicSharedMemorySize, FSM);
    dim3 gattn(SQL / 64, NHD, BB);   // 768 CTAs
    flash_hmma<<<gattn, 128, FSM>>>(qh, kh, vh, P2, mask, out);
}

// round 16
// speedup vs baseline: 1.0319x; 1.0319x over previous
#include <cuda_runtime.h>
#include <cuda_fp16.h>
#include <cstdint>

#define BB  8
#define SQL 512
#define SKL 512
#define HH  768
#define NHD 12
#define DHD 64
#define MROWS (BB * SQL)   // 4096

#define C2 0.1803368801111244f   // 0.125 * log2(e)

// ---------------- scratch ----------------
__device__ float g_P2[SQL * SKL];
__device__ __half g_qh[MROWS * HH];
__device__ __half g_kh[MROWS * HH];
__device__ __half g_vh[MROWS * HH];
__device__ __half g_hid[MROWS * HH];
__device__ __half g_ctx[MROWS * HH];
__device__ __half g_w[3 * HH * HH];

// ---------------- helpers ----------------
__device__ __forceinline__ float ex2f(float x) {
    float y;
    asm("ex2.approx.ftz.f32 %0, %1;" : "=f"(y) : "f"(x));
    return y;
}
__device__ __forceinline__ uint32_t smem_u32(const void* p) {
    uint32_t a;
    asm("{ .reg .u64 t; cvta.to.shared.u64 t, %1; cvt.u32.u64 %0, t; }" : "=r"(a) : "l"(p));
    return a;
}
__device__ __forceinline__ void cpa16(uint32_t dst, const void* src) {
    asm volatile("cp.async.cg.shared.global [%0], [%1], 16;" :: "r"(dst), "l"(src));
}
#define CPA_COMMIT() asm volatile("cp.async.commit_group;" ::: "memory")
#define CPA_WAIT(n)  asm volatile("cp.async.wait_group %0;" :: "n"(n) : "memory")

__device__ __forceinline__ void mma16816(float* d, const uint32_t* a, const uint32_t* b)
{
    asm volatile(
        "mma.sync.aligned.m16n8k16.row.col.f32.f16.f16.f32 "
        "{%0,%1,%2,%3}, {%4,%5,%6,%7}, {%8,%9}, {%0,%1,%2,%3};"
        : "+f"(d[0]), "+f"(d[1]), "+f"(d[2]), "+f"(d[3])
        : "r"(a[0]), "r"(a[1]), "r"(a[2]), "r"(a[3]), "r"(b[0]), "r"(b[1]));
}
__device__ __forceinline__ void ldmx4(uint32_t* r, uint32_t addr)
{
    asm volatile("ldmatrix.sync.aligned.m8n8.x4.shared.b16 {%0,%1,%2,%3}, [%4];"
                 : "=r"(r[0]), "=r"(r[1]), "=r"(r[2]), "=r"(r[3]) : "r"(addr));
}
__device__ __forceinline__ void ldmx4t(uint32_t* r, uint32_t addr)
{
    asm volatile("ldmatrix.sync.aligned.m8n8.x4.trans.shared.b16 {%0,%1,%2,%3}, [%4];"
                 : "=r"(r[0]), "=r"(r[1]), "=r"(r[2]), "=r"(r[3]) : "r"(addr));
}
__device__ __forceinline__ uint32_t pack_hf2(float a, float b) {
    __half2 h = __floats2half2_rn(a, b);
    return *(uint32_t*)&h;
}

// ---------------------------------------------------------------------------
// fp32 -> fp16 conversion, 5 arrays fused (no smem).
// ---------------------------------------------------------------------------
__global__ void cvt_all(
    const float* __restrict__ hidden, const float* __restrict__ context,
    const float* __restrict__ Wq, const float* __restrict__ Wk, const float* __restrict__ Wv,
    __half* __restrict__ hh, __half* __restrict__ ch, __half* __restrict__ w)
{
    const int y = blockIdx.y;
    const float* x;
    __half* hi;
    int n4;
    const int nA4 = MROWS * HH / 4, nW4 = HH * HH / 4;
    switch (y) {
        case 0: x = hidden;  hi = hh;              n4 = nA4; break;
        case 1: x = context; hi = ch;              n4 = nA4; break;
        case 2: x = Wq;      hi = w;               n4 = nW4; break;
        case 3: x = Wk;      hi = w + HH * HH;     n4 = nW4; break;
        default:x = Wv;      hi = w + 2 * HH * HH; n4 = nW4; break;
    }
    int i = blockIdx.x * blockDim.x + threadIdx.x;
    if (i >= n4) return;
    float4 v = ((const float4*)x)[i];
    __half2 a, b;
    a.x = __float2half_rn(v.x); a.y = __float2half_rn(v.y);
    b.x = __float2half_rn(v.z); b.y = __float2half_rn(v.w);
    ((__half2*)hi)[2 * i] = a; ((__half2*)hi)[2 * i + 1] = b;
}

// ---------------------------------------------------------------------------
// QKV projection: 1-term fp16 HMMA, BK=64, 2-stage, two-barrier (R10 form).
// ---------------------------------------------------------------------------
#define QPAD 72
#define QTIL 18432
#define QSTG 36864

__global__ __launch_bounds__(256, 2) void qkv_hmma(
    const __half* __restrict__ hid, const __half* __restrict__ ctx,
    const __half* __restrict__ w,
    const float* __restrict__ bq, const float* __restrict__ bk, const float* __restrict__ bv,
    const float* __restrict__ pos,
    __half* __restrict__ qh, __half* __restrict__ kh, __half* __restrict__ vh)
{
    extern __shared__ char smc[];
    const uint32_t sb = smem_u32(smc);

    const int z = blockIdx.z;
    const __half* A = (z == 0) ? hid : ctx;
    const __half* B = w + (size_t)z * HH * HH;
    const float* bias = (z == 0) ? bq : ((z == 1) ? bk : bv);
    __half* outp = (z == 0) ? qh : ((z == 1) ? kh : vh);

    const int t    = threadIdx.x;
    const int lane = t & 31;
    const int wid  = t >> 5;
    const int wm   = wid & 3;
    const int wn   = wid >> 2;
    const int g    = lane >> 2;
    const int tig  = lane & 3;
    const int m0   = blockIdx.y << 7;
    const int n0   = blockIdx.x << 7;

    const uint32_t a_off = ((wm * 32 + (lane & 15)) * QPAD + ((lane >> 4) << 3)) * 2;
    const uint32_t b_off = ((wn * 64 + (lane & 7) + ((lane & 16) ? 8 : 0)) * QPAD
                            + (((lane >> 3) & 1) << 3)) * 2;

    float acc[2][8][4];
#pragma unroll
    for (int i = 0; i < 2; i++)
#pragma unroll
        for (int j = 0; j < 8; j++)
#pragma unroll
            for (int c = 0; c < 4; c++) acc[i][j][c] = 0.0f;

    auto issue = [&](int kt, int stg) {
        const int k0 = kt << 6;
        const uint32_t base = sb + stg * QSTG;
#pragma unroll
        for (int i = 0; i < 4; i++) {
            int idx = t + (i << 8);
            int row = idx >> 3;
            int c   = (idx & 7) << 3;
            uint32_t so = row * 144 + c * 2;
            cpa16(base + so,        A + (size_t)(m0 + row) * HH + k0 + c);
            cpa16(base + QTIL + so, B + (size_t)(n0 + row) * HH + k0 + c);
        }
    };

    issue(0, 0);
    CPA_COMMIT();

    const int NT = HH / 64;   // 12
    for (int kt = 0; kt < NT; kt++) {
        if (kt + 1 < NT) {
            issue(kt + 1, (kt + 1) & 1);
            CPA_COMMIT();
            CPA_WAIT(1);
        } else {
            CPA_WAIT(0);
        }
        __syncthreads();

        const uint32_t stga = sb + (kt & 1) * QSTG;
        const uint32_t pA = stga + a_off;
        const uint32_t pB = stga + QTIL + b_off;

#pragma unroll
        for (int kk = 0; kk < 4; kk++) {
            const uint32_t kb = kk * 32;
            uint32_t bfr[8][2];
#pragma unroll
            for (int np = 0; np < 4; np++) {
                uint32_t r[4];
                ldmx4(r, pB + np * (16 * QPAD * 2) + kb);
                bfr[2 * np][0] = r[0];     bfr[2 * np][1] = r[1];
                bfr[2 * np + 1][0] = r[2]; bfr[2 * np + 1][1] = r[3];
            }
            uint32_t af[2][4];
            ldmx4(af[0], pA + kb);
            ldmx4(af[1], pA + 16 * QPAD * 2 + kb);
#pragma unroll
            for (int mt = 0; mt < 2; mt++)
#pragma unroll
                for (int nt = 0; nt < 8; nt++)
                    mma16816(acc[mt][nt], af[mt], bfr[nt]);
        }
        __syncthreads();
    }

#pragma unroll
    for (int mt = 0; mt < 2; mt++) {
#pragma unroll
        for (int nt = 0; nt < 8; nt++) {
            int m = m0 + wm * 32 + mt * 16 + g;
            int n = n0 + wn * 64 + nt * 8 + 2 * tig;
            float b0 = bias[n], b1 = bias[n + 1];
#pragma unroll
            for (int half = 0; half < 2; half++) {
                int mm = m + half * 8;
                float f0 = acc[mt][nt][2 * half]     + b0;
                float f1 = acc[mt][nt][2 * half + 1] + b1;
                if (z == 1) {
                    f0 += pos[(mm & (SKL - 1)) * DHD + (n & (DHD - 1))];
                    f1 += pos[(mm & (SKL - 1)) * DHD + ((n + 1) & (DHD - 1))];
                }
                *(uint32_t*)(outp + (size_t)mm * HH + n) = pack_hf2(f0, f1);
            }
        }
    }
}

// ---------------------------------------------------------------------------
// P2 = (pos @ pos^T) * C2  — 64x64 tiles, 64 CTAs (R10 form)
// ---------------------------------------------------------------------------
__global__ __launch_bounds__(128) void pos_gemm(
    const float* __restrict__ A, float* __restrict__ out)
{
    __shared__ float As[64][68];
    __shared__ float Bs[64][68];

    const int t  = threadIdx.x;
    const int m0 = blockIdx.y << 6;
    const int n0 = blockIdx.x << 6;
    const int tm = (t >> 3) << 2;
    const int tn = (t & 7) << 3;

#pragma unroll
    for (int i = 0; i < 8; i++) {
        int idx = t + (i << 7);
        int row = idx >> 4;
        int c4  = (idx & 15) << 2;
        float4 va = *(const float4*)(A + (size_t)(m0 + row) * DHD + c4);
        As[c4 + 0][row] = va.x; As[c4 + 1][row] = va.y;
        As[c4 + 2][row] = va.z; As[c4 + 3][row] = va.w;
        float4 vb = *(const float4*)(A + (size_t)(n0 + row) * DHD + c4);
        Bs[c4 + 0][row] = vb.x; Bs[c4 + 1][row] = vb.y;
        Bs[c4 + 2][row] = vb.z; Bs[c4 + 3][row] = vb.w;
    }
    __syncthreads();

    float acc[4][8];
#pragma unroll
    for (int i = 0; i < 4; i++)
#pragma unroll
        for (int j = 0; j < 8; j++) acc[i][j] = 0.0f;

#pragma unroll 8
    for (int kk = 0; kk < 64; kk++) {
        float a[4], b[8];
        *(float4*)a = *(const float4*)&As[kk][tm];
        *(float4*)(b + 0) = *(const float4*)&Bs[kk][tn];
        *(float4*)(b + 4) = *(const float4*)&Bs[kk][tn + 4];
#pragma unroll
        for (int i = 0; i < 4; i++)
#pragma unroll
            for (int j = 0; j < 8; j++)
                acc[i][j] += a[i] * b[j];
    }

#pragma unroll
    for (int i = 0; i < 4; i++)
#pragma unroll
        for (int j = 0; j < 8; j++)
            out[(size_t)(m0 + tm + i) * SKL + n0 + tn + j] = acc[i][j] * C2;
}

// ---------------------------------------------------------------------------
// Flash attention: 64 q-rows/CTA, 128 threads, occ 4, hoisted Q,
// single barrier per k-tile, 2-stage KV (R13/R14 form — measured best).
// smem: Q 9216 | KV 2x18432 | mask 2048 = 48128
// ---------------------------------------------------------------------------
#define FP   72
#define OKV  9216
#define KSTG 18432
#define KTIL 9216
#define OMB  (OKV + 2 * KSTG)   // 46080
#define FSM  (OMB + 2048)       // 48128

__global__ __launch_bounds__(128, 4) void flash_hmma(
    const __half* __restrict__ qh,
    const __half* __restrict__ kh, const __half* __restrict__ vh,
    const float* __restrict__ P2, const int* __restrict__ mask,
    float* __restrict__ out)
{
    extern __shared__ char smc[];
    __half* sQh = (__half*)(smc);
    float*  smb = (float*)(smc + OMB);
    const uint32_t sb = smem_u32(smc);

    const int t    = threadIdx.x;
    const int lane = t & 31;
    const int w    = t >> 5;
    const int g    = lane >> 2;
    const int tig  = lane & 3;
    const int wr   = w << 4;
    const int b    = blockIdx.z;
    const int h    = blockIdx.y;
    const int q0   = blockIdx.x << 6;

    const uint32_t q_off = ((wr + (lane & 15)) * FP + ((lane >> 4) << 3)) * 2;
    const uint32_t k_off = (((lane & 7) + ((lane & 16) ? 8 : 0)) * FP
                            + (((lane >> 3) & 1) << 3)) * 2;
    const uint32_t v_off = ((lane & 15) * FP + ((lane >> 4) << 3)) * 2;

    auto issue_kv = [&](int kt, int stg) {
        const uint32_t base = sb + OKV + stg * KSTG;
#pragma unroll
        for (int i = 0; i < 4; i++) {
            int idx = t + (i << 7);
            int row = idx >> 3;
            int c   = (idx & 7) << 3;
            uint32_t so = row * 144 + c * 2;
            size_t gg = (size_t)(b * SKL + kt * 64 + row) * HH + h * DHD + c;
            cpa16(base + so,        kh + gg);
            cpa16(base + KTIL + so, vh + gg);
        }
    };

    issue_kv(0, 0);
    CPA_COMMIT();

#pragma unroll
    for (int i = 0; i < 4; i++) {
        int idx = t + (i << 7);
        int row = idx >> 3;
        int c   = (idx & 7) << 3;
        size_t gsrc = (size_t)(b * SQL + q0 + row) * HH + h * DHD + c;
        *(uint4*)(sQh + row * FP + c) = *(const uint4*)(qh + gsrc);
    }
#pragma unroll
    for (int i = 0; i < 4; i++) {
        int idx = t + (i << 7);
        smb[idx] = (mask[b * SKL + idx] == 0) ? -1e30f : 0.0f;
    }
    __syncthreads();

    uint32_t qfr[4][4];
#pragma unroll
    for (int kk = 0; kk < 4; kk++)
        ldmx4(qfr[kk], sb + q_off + kk * 32);

    float o[8][4];
#pragma unroll
    for (int i = 0; i < 8; i++)
#pragma unroll
        for (int c = 0; c < 4; c++) o[i][c] = 0.0f;
    float m0r = -1e30f, m1r = -1e30f, l0r = 0.0f, l1r = 0.0f;

    const int NT = SKL / 64;   // 8
    for (int kt = 0; kt < NT; kt++) {
        CPA_WAIT(0);
        __syncthreads();
        if (kt + 1 < NT) {
            issue_kv(kt + 1, (kt + 1) & 1);
            CPA_COMMIT();
        }

        const int stg = kt & 1;
        const uint32_t kvb = sb + OKV + stg * KSTG;
        const uint32_t pK = kvb + k_off;
        const uint32_t pV = kvb + KTIL + v_off;

        // ---- S = Q K'^T ----
        float s[8][4];
#pragma unroll
        for (int nt = 0; nt < 8; nt++)
#pragma unroll
            for (int c = 0; c < 4; c++) s[nt][c] = 0.0f;

#pragma unroll
        for (int kk = 0; kk < 4; kk++) {
            const uint32_t kb = kk * 32;
#pragma unroll
            for (int np = 0; np < 4; np++) {
                uint32_t bh4[4];
                ldmx4(bh4, pK + np * (16 * FP * 2) + kb);
                mma16816(s[2 * np],     qfr[kk], bh4 + 0);
                mma16816(s[2 * np + 1], qfr[kk], bh4 + 2);
            }
        }

        // ---- bias + mask + online softmax ----
        const float* pg0 = P2 + (size_t)(q0 + wr + g) * SKL + kt * 64;
        const float* pg1 = pg0 + 8 * SKL;
        const float* mrow = smb + kt * 64;
        float vm0 = -1e30f, vm1 = -1e30f;
#pragma unroll
        for (int nt = 0; nt < 8; nt++) {
            int cc = nt * 8 + 2 * tig;
            float2 p0 = *(const float2*)(pg0 + cc);
            float2 p1 = *(const float2*)(pg1 + cc);
            float mb0 = mrow[cc], mb1 = mrow[cc + 1];
            s[nt][0] = fmaf(s[nt][0], C2, p0.x) + mb0;
            s[nt][1] = fmaf(s[nt][1], C2, p0.y) + mb1;
            s[nt][2] = fmaf(s[nt][2], C2, p1.x) + mb0;
            s[nt][3] = fmaf(s[nt][3], C2, p1.y) + mb1;
            vm0 = fmaxf(vm0, fmaxf(s[nt][0], s[nt][1]));
            vm1 = fmaxf(vm1, fmaxf(s[nt][2], s[nt][3]));
        }
        vm0 = fmaxf(vm0, __shfl_xor_sync(0xffffffffu, vm0, 1));
        vm0 = fmaxf(vm0, __shfl_xor_sync(0xffffffffu, vm0, 2));
        vm1 = fmaxf(vm1, __shfl_xor_sync(0xffffffffu, vm1, 1));
        vm1 = fmaxf(vm1, __shfl_xor_sync(0xffffffffu, vm1, 2));
        float mn0 = fmaxf(m0r, vm0), mn1 = fmaxf(m1r, vm1);
        float cr0 = ex2f(m0r - mn0), cr1 = ex2f(m1r - mn1);
        m0r = mn0; m1r = mn1;

        float rs0 = 0.0f, rs1 = 0.0f;
#pragma unroll
        for (int nt = 0; nt < 8; nt++) {
            s[nt][0] = ex2f(s[nt][0] - mn0); rs0 += s[nt][0];
            s[nt][1] = ex2f(s[nt][1] - mn0); rs0 += s[nt][1];
            s[nt][2] = ex2f(s[nt][2] - mn1); rs1 += s[nt][2];
            s[nt][3] = ex2f(s[nt][3] - mn1); rs1 += s[nt][3];
        }
        rs0 += __shfl_xor_sync(0xffffffffu, rs0, 1);
        rs0 += __shfl_xor_sync(0xffffffffu, rs0, 2);
        rs1 += __shfl_xor_sync(0xffffffffu, rs1, 1);
        rs1 += __shfl_xor_sync(0xffffffffu, rs1, 2);
        l0r = l0r * cr0 + rs0;
        l1r = l1r * cr1 + rs1;
#pragma unroll
        for (int nt = 0; nt < 8; nt++) {
            o[nt][0] *= cr0; o[nt][1] *= cr0;
            o[nt][2] *= cr1; o[nt][3] *= cr1;
        }

        // ---- O += P @ V ----
#pragma unroll
        for (int j = 0; j < 4; j++) {
            const int na = 2 * j, nb = 2 * j + 1;
            uint32_t aph[4];
            aph[0] = pack_hf2(s[na][0], s[na][1]);
            aph[1] = pack_hf2(s[na][2], s[na][3]);
            aph[2] = pack_hf2(s[nb][0], s[nb][1]);
            aph[3] = pack_hf2(s[nb][2], s[nb][3]);
            const uint32_t jv = pV + j * (16 * FP * 2);
#pragma unroll
            for (int vp = 0; vp < 4; vp++) {
                uint32_t bv4[4];
                ldmx4t(bv4, jv + vp * 32);
                mma16816(o[2 * vp],     aph, bv4 + 0);
                mma16816(o[2 * vp + 1], aph, bv4 + 2);
            }
        }
    }

    float inv0 = 1.0f / l0r, inv1 = 1.0f / l1r;
    float* or0 = out + (size_t)(b * SQL + q0 + wr + g) * HH + h * DHD;
    float* or1 = or0 + 8 * HH;
#pragma unroll
    for (int ntv = 0; ntv < 8; ntv++) {
        int cc = ntv * 8 + 2 * tig;
        float2 w0 = make_float2(o[ntv][0] * inv0, o[ntv][1] * inv0);
        float2 w1 = make_float2(o[ntv][2] * inv1, o[ntv][3] * inv1);
        *(float2*)(or0 + cc) = w0;
        *(float2*)(or1 + cc) = w1;
    }
}

// ---------------------------------------------------------------------------
extern "C" void kernel_launch(void* const* d_in, const int* in_sizes, int n_in,
                              void* d_out, int out_size)
{
    const float* hidden  = (const float*)d_in[0];
    const float* context = (const float*)d_in[1];
    const int*   mask    = (const int*)d_in[2];
    const float* Wq      = (const float*)d_in[3];
    const float* bq      = (const float*)d_in[4];
    const float* Wk      = (const float*)d_in[5];
    const float* bk      = (const float*)d_in[6];
    const float* Wv      = (const float*)d_in[7];
    const float* bv      = (const float*)d_in[8];
    const float* pos     = (const float*)d_in[9];
    float* out = (float*)d_out;

    float* P2;
    cudaGetSymbolAddress((void**)&P2, g_P2);
    __half *qh, *kh, *vh, *hh, *ch, *w;
    cudaGetSymbolAddress((void**)&qh, g_qh);
    cudaGetSymbolAddress((void**)&kh, g_kh);
    cudaGetSymbolAddress((void**)&vh, g_vh);
    cudaGetSymbolAddress((void**)&hh, g_hid);
    cudaGetSymbolAddress((void**)&ch, g_ctx);
    cudaGetSymbolAddress((void**)&w,  g_w);

    const int nA4 = MROWS * HH / 4;
    dim3 gcvt((nA4 + 255) / 256, 5);
    cvt_all<<<gcvt, 256>>>(hidden, context, Wq, Wk, Wv, hh, ch, w);

    cudaFuncSetAttribute(qkv_hmma, cudaFuncAttributeMaxDynamicSharedMemorySize, 2 * QSTG);
    dim3 gproj(HH / 128, MROWS / 128, 3);
    qkv_hmma<<<gproj, 256, 2 * QSTG>>>(hh, ch, w, bq, bk, bv, pos, qh, kh, vh);

    dim3 gpos(SKL / 64, SQL / 64);
    pos_gemm<<<gpos, 128>>>(pos, P2);

    cudaFuncSetAttribute(flash_hmma, cudaFuncAttributeMaxDynamicSharedMemorySize, FSM);
    dim3 gattn(SQL / 64, NHD, BB);   // 768 CTAs
    flash_hmma<<<gattn, 128, FSM>>>(qh, kh, vh, P2, mask, out);
}

// round 17
// speedup vs baseline: 1.0536x; 1.0210x over previous
#include <cuda_runtime.h>
#include <cuda_fp16.h>
#include <cstdint>

#define BB  8
#define SQL 512
#define SKL 512
#define HH  768
#define NHD 12
#define DHD 64
#define MROWS (BB * SQL)   // 4096

#define C2 0.1803368801111244f   // 0.125 * log2(e)

// ---------------- scratch ----------------
__device__ float g_P2[SQL * SKL];
__device__ __half g_qh[MROWS * HH];
__device__ __half g_kh[MROWS * HH];
__device__ __half g_vh[MROWS * HH];
__device__ __half g_hid[MROWS * HH];
__device__ __half g_ctx[MROWS * HH];
__device__ __half g_w[3 * HH * HH];

// ---------------- helpers ----------------
__device__ __forceinline__ float ex2f(float x) {
    float y;
    asm("ex2.approx.ftz.f32 %0, %1;" : "=f"(y) : "f"(x));
    return y;
}
__device__ __forceinline__ uint32_t smem_u32(const void* p) {
    uint32_t a;
    asm("{ .reg .u64 t; cvta.to.shared.u64 t, %1; cvt.u32.u64 %0, t; }" : "=r"(a) : "l"(p));
    return a;
}
__device__ __forceinline__ void cpa16(uint32_t dst, const void* src) {
    asm volatile("cp.async.cg.shared.global [%0], [%1], 16;" :: "r"(dst), "l"(src));
}
#define CPA_COMMIT() asm volatile("cp.async.commit_group;" ::: "memory")
#define CPA_WAIT(n)  asm volatile("cp.async.wait_group %0;" :: "n"(n) : "memory")

__device__ __forceinline__ void mma16816(float* d, const uint32_t* a, const uint32_t* b)
{
    asm volatile(
        "mma.sync.aligned.m16n8k16.row.col.f32.f16.f16.f32 "
        "{%0,%1,%2,%3}, {%4,%5,%6,%7}, {%8,%9}, {%0,%1,%2,%3};"
        : "+f"(d[0]), "+f"(d[1]), "+f"(d[2]), "+f"(d[3])
        : "r"(a[0]), "r"(a[1]), "r"(a[2]), "r"(a[3]), "r"(b[0]), "r"(b[1]));
}
__device__ __forceinline__ void ldmx4(uint32_t* r, uint32_t addr)
{
    asm volatile("ldmatrix.sync.aligned.m8n8.x4.shared.b16 {%0,%1,%2,%3}, [%4];"
                 : "=r"(r[0]), "=r"(r[1]), "=r"(r[2]), "=r"(r[3]) : "r"(addr));
}
__device__ __forceinline__ void ldmx4t(uint32_t* r, uint32_t addr)
{
    asm volatile("ldmatrix.sync.aligned.m8n8.x4.trans.shared.b16 {%0,%1,%2,%3}, [%4];"
                 : "=r"(r[0]), "=r"(r[1]), "=r"(r[2]), "=r"(r[3]) : "r"(addr));
}
__device__ __forceinline__ uint32_t pack_hf2(float a, float b) {
    __half2 h = __floats2half2_rn(a, b);
    return *(uint32_t*)&h;
}

// ---------------------------------------------------------------------------
// fp32 -> fp16 conversion, 5 arrays fused.
// ---------------------------------------------------------------------------
__global__ void cvt_all(
    const float* __restrict__ hidden, const float* __restrict__ context,
    const float* __restrict__ Wq, const float* __restrict__ Wk, const float* __restrict__ Wv,
    __half* __restrict__ hh, __half* __restrict__ ch, __half* __restrict__ w)
{
    const int y = blockIdx.y;
    const float* x;
    __half* hi;
    int n4;
    const int nA4 = MROWS * HH / 4, nW4 = HH * HH / 4;
    switch (y) {
        case 0: x = hidden;  hi = hh;              n4 = nA4; break;
        case 1: x = context; hi = ch;              n4 = nA4; break;
        case 2: x = Wq;      hi = w;               n4 = nW4; break;
        case 3: x = Wk;      hi = w + HH * HH;     n4 = nW4; break;
        default:x = Wv;      hi = w + 2 * HH * HH; n4 = nW4; break;
    }
    int i = blockIdx.x * blockDim.x + threadIdx.x;
    if (i >= n4) return;
    float4 v = ((const float4*)x)[i];
    __half2 a, b;
    a.x = __float2half_rn(v.x); a.y = __float2half_rn(v.y);
    b.x = __float2half_rn(v.z); b.y = __float2half_rn(v.w);
    ((__half2*)hi)[2 * i] = a; ((__half2*)hi)[2 * i + 1] = b;
}

// ---------------------------------------------------------------------------
// QKV projection: 1-term fp16 HMMA, BK=64 (12 fat iterations), double-buffered.
// CTA 128x128, 256 threads. (R10 form — measured optimum)
// ---------------------------------------------------------------------------
#define QPAD 72
#define QTIL 18432          // 128 x 72 halves
#define QSTG 36864          // A + B

__global__ __launch_bounds__(256, 2) void qkv_hmma(
    const __half* __restrict__ hid, const __half* __restrict__ ctx,
    const __half* __restrict__ w,
    const float* __restrict__ bq, const float* __restrict__ bk, const float* __restrict__ bv,
    const float* __restrict__ pos,
    __half* __restrict__ qh, __half* __restrict__ kh, __half* __restrict__ vh)
{
    extern __shared__ char smc[];
    const uint32_t sb = smem_u32(smc);

    const int z = blockIdx.z;
    const __half* A = (z == 0) ? hid : ctx;
    const __half* B = w + (size_t)z * HH * HH;
    const float* bias = (z == 0) ? bq : ((z == 1) ? bk : bv);
    __half* outp = (z == 0) ? qh : ((z == 1) ? kh : vh);

    const int t    = threadIdx.x;
    const int lane = t & 31;
    const int wid  = t >> 5;
    const int wm   = wid & 3;
    const int wn   = wid >> 2;
    const int g    = lane >> 2;
    const int tig  = lane & 3;
    const int m0   = blockIdx.y << 7;
    const int n0   = blockIdx.x << 7;

    const uint32_t a_off = ((wm * 32 + (lane & 15)) * QPAD + ((lane >> 4) << 3)) * 2;
    const uint32_t b_off = ((wn * 64 + (lane & 7) + ((lane & 16) ? 8 : 0)) * QPAD
                            + (((lane >> 3) & 1) << 3)) * 2;

    float acc[2][8][4];
#pragma unroll
    for (int i = 0; i < 2; i++)
#pragma unroll
        for (int j = 0; j < 8; j++)
#pragma unroll
            for (int c = 0; c < 4; c++) acc[i][j][c] = 0.0f;

    auto issue = [&](int kt, int stg) {
        const int k0 = kt << 6;
        const uint32_t base = sb + stg * QSTG;
#pragma unroll
        for (int i = 0; i < 4; i++) {
            int idx = t + (i << 8);
            int row = idx >> 3;
            int c   = (idx & 7) << 3;
            uint32_t so = row * 144 + c * 2;
            cpa16(base + so,        A + (size_t)(m0 + row) * HH + k0 + c);
            cpa16(base + QTIL + so, B + (size_t)(n0 + row) * HH + k0 + c);
        }
    };

    issue(0, 0);
    CPA_COMMIT();

    const int NT = HH / 64;   // 12
    for (int kt = 0; kt < NT; kt++) {
        if (kt + 1 < NT) {
            issue(kt + 1, (kt + 1) & 1);
            CPA_COMMIT();
            CPA_WAIT(1);
        } else {
            CPA_WAIT(0);
        }
        __syncthreads();

        const uint32_t stga = sb + (kt & 1) * QSTG;
        const uint32_t pA = stga + a_off;
        const uint32_t pB = stga + QTIL + b_off;

#pragma unroll
        for (int kk = 0; kk < 4; kk++) {
            const uint32_t kb = kk * 32;
            uint32_t bfr[8][2];
#pragma unroll
            for (int np = 0; np < 4; np++) {
                uint32_t r[4];
                ldmx4(r, pB + np * (16 * QPAD * 2) + kb);
                bfr[2 * np][0] = r[0];     bfr[2 * np][1] = r[1];
                bfr[2 * np + 1][0] = r[2]; bfr[2 * np + 1][1] = r[3];
            }
            uint32_t af[2][4];
            ldmx4(af[0], pA + kb);
            ldmx4(af[1], pA + 16 * QPAD * 2 + kb);
#pragma unroll
            for (int mt = 0; mt < 2; mt++)
#pragma unroll
                for (int nt = 0; nt < 8; nt++)
                    mma16816(acc[mt][nt], af[mt], bfr[nt]);
        }
        __syncthreads();
    }

    // epilogue: +bias (+pos for K), single fp16 store
#pragma unroll
    for (int mt = 0; mt < 2; mt++) {
#pragma unroll
        for (int nt = 0; nt < 8; nt++) {
            int m = m0 + wm * 32 + mt * 16 + g;
            int n = n0 + wn * 64 + nt * 8 + 2 * tig;
            float b0 = bias[n], b1 = bias[n + 1];
#pragma unroll
            for (int half = 0; half < 2; half++) {
                int mm = m + half * 8;
                float f0 = acc[mt][nt][2 * half]     + b0;
                float f1 = acc[mt][nt][2 * half + 1] + b1;
                if (z == 1) {
                    f0 += pos[(mm & (SKL - 1)) * DHD + (n & (DHD - 1))];
                    f1 += pos[(mm & (SKL - 1)) * DHD + ((n + 1) & (DHD - 1))];
                }
                *(uint32_t*)(outp + (size_t)mm * HH + n) = pack_hf2(f0, f1);
            }
        }
    }
}

// ---------------------------------------------------------------------------
// P2 = (pos @ pos^T) * C2  — 64x64 tiles, 64 CTAs
// ---------------------------------------------------------------------------
__global__ __launch_bounds__(128) void pos_gemm(
    const float* __restrict__ A, float* __restrict__ out)
{
    __shared__ float As[64][68];
    __shared__ float Bs[64][68];

    const int t  = threadIdx.x;
    const int m0 = blockIdx.y << 6;
    const int n0 = blockIdx.x << 6;
    const int tm = (t >> 3) << 2;
    const int tn = (t & 7) << 3;

#pragma unroll
    for (int i = 0; i < 8; i++) {
        int idx = t + (i << 7);
        int row = idx >> 4;
        int c4  = (idx & 15) << 2;
        float4 va = *(const float4*)(A + (size_t)(m0 + row) * DHD + c4);
        As[c4 + 0][row] = va.x; As[c4 + 1][row] = va.y;
        As[c4 + 2][row] = va.z; As[c4 + 3][row] = va.w;
        float4 vb = *(const float4*)(A + (size_t)(n0 + row) * DHD + c4);
        Bs[c4 + 0][row] = vb.x; Bs[c4 + 1][row] = vb.y;
        Bs[c4 + 2][row] = vb.z; Bs[c4 + 3][row] = vb.w;
    }
    __syncthreads();

    float acc[4][8];
#pragma unroll
    for (int i = 0; i < 4; i++)
#pragma unroll
        for (int j = 0; j < 8; j++) acc[i][j] = 0.0f;

#pragma unroll 8
    for (int kk = 0; kk < 64; kk++) {
        float a[4], b[8];
        *(float4*)a = *(const float4*)&As[kk][tm];
        *(float4*)(b + 0) = *(const float4*)&Bs[kk][tn];
        *(float4*)(b + 4) = *(const float4*)&Bs[kk][tn + 4];
#pragma unroll
        for (int i = 0; i < 4; i++)
#pragma unroll
            for (int j = 0; j < 8; j++)
                acc[i][j] += a[i] * b[j];
    }

#pragma unroll
    for (int i = 0; i < 4; i++)
#pragma unroll
        for (int j = 0; j < 8; j++)
            out[(size_t)(m0 + tm + i) * SKL + n0 + tn + j] = acc[i][j] * C2;
}

// ---------------------------------------------------------------------------
// Flash attention: 64 q-rows/CTA, 128 threads (4 warps x 16 rows), occ 4.
// Q fragments hoisted to registers. Two-phase iteration (R10 form).
// smem: Q 9216 | KV 2x18432 | mask 2048 = 48128
// ---------------------------------------------------------------------------
#define FP   72
#define OKV  9216
#define KSTG 18432
#define KTIL 9216
#define OMB  (OKV + 2 * KSTG)   // 46080
#define FSM  (OMB + 2048)       // 48128

__global__ __launch_bounds__(128, 4) void flash_hmma(
    const __half* __restrict__ qh,
    const __half* __restrict__ kh, const __half* __restrict__ vh,
    const float* __restrict__ P2, const int* __restrict__ mask,
    float* __restrict__ out)
{
    extern __shared__ char smc[];
    __half* sQh = (__half*)(smc);
    float*  smb = (float*)(smc + OMB);
    const uint32_t sb = smem_u32(smc);

    const int t    = threadIdx.x;
    const int lane = t & 31;
    const int w    = t >> 5;          // 0..3
    const int g    = lane >> 2;
    const int tig  = lane & 3;
    const int wr   = w << 4;          // warp's 16-row strip within 64
    const int b    = blockIdx.z;
    const int h    = blockIdx.y;
    const int q0   = blockIdx.x << 6; // 64-row q tile

    const uint32_t q_off = ((wr + (lane & 15)) * FP + ((lane >> 4) << 3)) * 2;
    const uint32_t k_off = (((lane & 7) + ((lane & 16) ? 8 : 0)) * FP
                            + (((lane >> 3) & 1) << 3)) * 2;
    const uint32_t v_off = ((lane & 15) * FP + ((lane >> 4) << 3)) * 2;

    auto issue_kv = [&](int kt, int stg) {
        const uint32_t base = sb + OKV + stg * KSTG;
#pragma unroll
        for (int i = 0; i < 4; i++) {
            int idx = t + (i << 7);
            int row = idx >> 3;
            int c   = (idx & 7) << 3;
            uint32_t so = row * 144 + c * 2;
            size_t gg = (size_t)(b * SKL + kt * 64 + row) * HH + h * DHD + c;
            cpa16(base + so,        kh + gg);
            cpa16(base + KTIL + so, vh + gg);
        }
    };

    issue_kv(0, 0);
    CPA_COMMIT();

    // Q tile (64 x 64) + mask row (512 floats)
#pragma unroll
    for (int i = 0; i < 4; i++) {
        int idx = t + (i << 7);
        int row = idx >> 3;
        int c   = (idx & 7) << 3;
        size_t gsrc = (size_t)(b * SQL + q0 + row) * HH + h * DHD + c;
        *(uint4*)(sQh + row * FP + c) = *(const uint4*)(qh + gsrc);
    }
#pragma unroll
    for (int i = 0; i < 4; i++) {
        int idx = t + (i << 7);
        smb[idx] = (mask[b * SKL + idx] == 0) ? -1e30f : 0.0f;
    }
    __syncthreads();

    // hoist Q fragments (constant across k-tiles)
    uint32_t qfr[4][4];
#pragma unroll
    for (int kk = 0; kk < 4; kk++)
        ldmx4(qfr[kk], sb + q_off + kk * 32);

    float o[8][4];
#pragma unroll
    for (int i = 0; i < 8; i++)
#pragma unroll
        for (int c = 0; c < 4; c++) o[i][c] = 0.0f;
    float m0r = -1e30f, m1r = -1e30f, l0r = 0.0f, l1r = 0.0f;

    const int NT = SKL / 64;   // 8
    for (int kt = 0; kt < NT; kt++) {
        if (kt + 1 < NT) {
            issue_kv(kt + 1, (kt + 1) & 1);
            CPA_COMMIT();
            CPA_WAIT(1);
        } else {
            CPA_WAIT(0);
        }
        __syncthreads();

        const int stg = kt & 1;
        const uint32_t kvb = sb + OKV + stg * KSTG;
        const uint32_t pK = kvb + k_off;
        const uint32_t pV = kvb + KTIL + v_off;

        // ---- S = Q K'^T ----
        float s[8][4];
#pragma unroll
        for (int nt = 0; nt < 8; nt++)
#pragma unroll
            for (int c = 0; c < 4; c++) s[nt][c] = 0.0f;

#pragma unroll
        for (int kk = 0; kk < 4; kk++) {
            const uint32_t kb = kk * 32;
#pragma unroll
            for (int np = 0; np < 4; np++) {
                uint32_t bh4[4];
                ldmx4(bh4, pK + np * (16 * FP * 2) + kb);
                mma16816(s[2 * np],     qfr[kk], bh4 + 0);
                mma16816(s[2 * np + 1], qfr[kk], bh4 + 2);
            }
        }

        // ---- bias + mask + online softmax ----
        const float* pg0 = P2 + (size_t)(q0 + wr + g) * SKL + kt * 64;
        const float* pg1 = pg0 + 8 * SKL;
        const float* mrow = smb + kt * 64;
        float vm0 = -1e30f, vm1 = -1e30f;
#pragma unroll
        for (int nt = 0; nt < 8; nt++) {
            int cc = nt * 8 + 2 * tig;
            float2 p0 = *(const float2*)(pg0 + cc);
            float2 p1 = *(const float2*)(pg1 + cc);
            float mb0 = mrow[cc], mb1 = mrow[cc + 1];
            s[nt][0] = fmaf(s[nt][0], C2, p0.x) + mb0;
            s[nt][1] = fmaf(s[nt][1], C2, p0.y) + mb1;
            s[nt][2] = fmaf(s[nt][2], C2, p1.x) + mb0;
            s[nt][3] = fmaf(s[nt][3], C2, p1.y) + mb1;
            vm0 = fmaxf(vm0, fmaxf(s[nt][0], s[nt][1]));
            vm1 = fmaxf(vm1, fmaxf(s[nt][2], s[nt][3]));
        }
        vm0 = fmaxf(vm0, __shfl_xor_sync(0xffffffffu, vm0, 1));
        vm0 = fmaxf(vm0, __shfl_xor_sync(0xffffffffu, vm0, 2));
        vm1 = fmaxf(vm1, __shfl_xor_sync(0xffffffffu, vm1, 1));
        vm1 = fmaxf(vm1, __shfl_xor_sync(0xffffffffu, vm1, 2));
        float mn0 = fmaxf(m0r, vm0), mn1 = fmaxf(m1r, vm1);
        float cr0 = ex2f(m0r - mn0), cr1 = ex2f(m1r - mn1);
        m0r = mn0; m1r = mn1;

        float rs0 = 0.0f, rs1 = 0.0f;
#pragma unroll
        for (int nt = 0; nt < 8; nt++) {
            s[nt][0] = ex2f(s[nt][0] - mn0); rs0 += s[nt][0];
            s[nt][1] = ex2f(s[nt][1] - mn0); rs0 += s[nt][1];
            s[nt][2] = ex2f(s[nt][2] - mn1); rs1 += s[nt][2];
            s[nt][3] = ex2f(s[nt][3] - mn1); rs1 += s[nt][3];
        }
        rs0 += __shfl_xor_sync(0xffffffffu, rs0, 1);
        rs0 += __shfl_xor_sync(0xffffffffu, rs0, 2);
        rs1 += __shfl_xor_sync(0xffffffffu, rs1, 1);
        rs1 += __shfl_xor_sync(0xffffffffu, rs1, 2);
        l0r = l0r * cr0 + rs0;
        l1r = l1r * cr1 + rs1;
#pragma unroll
        for (int nt = 0; nt < 8; nt++) {
            o[nt][0] *= cr0; o[nt][1] *= cr0;
            o[nt][2] *= cr1; o[nt][3] *= cr1;
        }

        // ---- O += P @ V ----
#pragma unroll
        for (int j = 0; j < 4; j++) {
            const int na = 2 * j, nb = 2 * j + 1;
            uint32_t aph[4];
            aph[0] = pack_hf2(s[na][0], s[na][1]);
            aph[1] = pack_hf2(s[na][2], s[na][3]);
            aph[2] = pack_hf2(s[nb][0], s[nb][1]);
            aph[3] = pack_hf2(s[nb][2], s[nb][3]);
            const uint32_t jv = pV + j * (16 * FP * 2);
#pragma unroll
            for (int vp = 0; vp < 4; vp++) {
                uint32_t bv4[4];
                ldmx4t(bv4, jv + vp * 32);
                mma16816(o[2 * vp],     aph, bv4 + 0);
                mma16816(o[2 * vp + 1], aph, bv4 + 2);
            }
        }
        __syncthreads();
    }

    float inv0 = 1.0f / l0r, inv1 = 1.0f / l1r;
    float* or0 = out + (size_t)(b * SQL + q0 + wr + g) * HH + h * DHD;
    float* or1 = or0 + 8 * HH;
#pragma unroll
    for (int ntv = 0; ntv < 8; ntv++) {
        int cc = ntv * 8 + 2 * tig;
        float2 w0 = make_float2(o[ntv][0] * inv0, o[ntv][1] * inv0);
        float2 w1 = make_float2(o[ntv][2] * inv1, o[ntv][3] * inv1);
        *(float2*)(or0 + cc) = w0;
        *(float2*)(or1 + cc) = w1;
    }
}

// ---------------------------------------------------------------------------
extern "C" void kernel_launch(void* const* d_in, const int* in_sizes, int n_in,
                              void* d_out, int out_size)
{
    const float* hidden  = (const float*)d_in[0];
    const float* context = (const float*)d_in[1];
    const int*   mask    = (const int*)d_in[2];
    const float* Wq      = (const float*)d_in[3];
    const float* bq      = (const float*)d_in[4];
    const float* Wk      = (const float*)d_in[5];
    const float* bk      = (const float*)d_in[6];
    const float* Wv      = (const float*)d_in[7];
    const float* bv      = (const float*)d_in[8];
    const float* pos     = (const float*)d_in[9];
    float* out = (float*)d_out;

    float* P2;
    cudaGetSymbolAddress((void**)&P2, g_P2);
    __half *qh, *kh, *vh, *hh, *ch, *w;
    cudaGetSymbolAddress((void**)&qh, g_qh);
    cudaGetSymbolAddress((void**)&kh, g_kh);
    cudaGetSymbolAddress((void**)&vh, g_vh);
    cudaGetSymbolAddress((void**)&hh, g_hid);
    cudaGetSymbolAddress((void**)&ch, g_ctx);
    cudaGetSymbolAddress((void**)&w,  g_w);

    const int nA4 = MROWS * HH / 4;
    dim3 gcvt((nA4 + 255) / 256, 5);
    cvt_all<<<gcvt, 256>>>(hidden, context, Wq, Wk, Wv, hh, ch, w);

    cudaFuncSetAttribute(qkv_hmma, cudaFuncAttributeMaxDynamicSharedMemorySize, 2 * QSTG);
    dim3 gproj(HH / 128, MROWS / 128, 3);
    qkv_hmma<<<gproj, 256, 2 * QSTG>>>(hh, ch, w, bq, bk, bv, pos, qh, kh, vh);

    dim3 gpos(SKL / 64, SQL / 64);
    pos_gemm<<<gpos, 128>>>(pos, P2);

    cudaFuncSetAttribute(flash_hmma, cudaFuncAttributeMaxDynamicSharedMemorySize, FSM);
    dim3 gattn(SQL / 64, NHD, BB);   // (8, 12, 8) = 768 CTAs
    flash_hmma<<<gattn, 128, FSM>>>(qh, kh, vh, P2, mask, out);
}